// round 10
// baseline (speedup 1.0000x reference)
#include <cuda_runtime.h>

#define LOG2E 1.4426950408889634f
#define NI 12                 // intervals per attention
#define NNODE 9               // Chebyshev nodes per interval (degree 8)
#define NODES (NI * NNODE)    // 108
#define NGRP 6                // node-groups for fused node eval (18 nodes each)

#define PROJ_KC 24            // 768 / 32
#define PROJ_KCH 32
#define MLP_KC 120            // 3840 / 32
#define MLP_KCH 32

#define FAT_NODE_BLOCKS (NGRP * 32)            // 192
#define FAT_PROJ_BLOCKS (PROJ_KC * 2 * 3)      // 144

// PDL primitives (sm_90+): dependent grid starts early; wait gates reads of
// the previous kernel's output; launch_dependents releases dependents early.
#define GDC_WAIT    asm volatile("griddepcontrol.wait;" ::: "memory")
#define GDC_RELEASE asm volatile("griddepcontrol.launch_dependents;" ::: "memory")

// ---------------- scratch (__device__ globals; allocation-free rule) -------
__device__ float  g_fused[32 * 2304];            // [sentence | scene | speaker]
__device__ float  g_h_part[MLP_KC * 32 * 256];   // mlp1 partials [kc][b][j]
__device__ float  g_pp[3 * PROJ_KC * 32 * 512];  // proj partials [task][kc][b][j]
__device__ float2 g_nodes[32 * NODES];           // fused node table [b][m] (num,den)
__device__ float  g_frange[32 * 2];              // fused range [b][min,max]

__constant__ float CHEB[9] = {1.f, 0.92387953f, 0.70710678f, 0.38268343f, 0.f,
                              -0.38268343f, -0.70710678f, -0.92387953f, -1.f};
__constant__ float LAMB[9] = {0.5f, -1.f, 1.f, -1.f, 1.f, -1.f, 1.f, -1.f, 0.5f};

__device__ __forceinline__ float ex2f(float x) {
    float y; asm("ex2.approx.f32 %0, %1;" : "=f"(y) : "f"(x)); return y;
}
__device__ __forceinline__ float wredsum(float v) {
#pragma unroll
    for (int o = 16; o > 0; o >>= 1) v += __shfl_xor_sync(0xffffffffu, v, o);
    return v;
}

__device__ __forceinline__ float interp_s(float x, float xmin, float w, float hw,
                                          float invw,
                                          const float* __restrict__ snum,
                                          const float* __restrict__ sden) {
    int c = (int)((x - xmin) * invw);
    c = (c < 0) ? 0 : ((c >= NI) ? NI - 1 : c);
    const float x0 = xmin + (c + 0.5f) * w;
    const int base = c * NNODE;
    float wn = 0.f, wd = 0.f, hitn = 0.f, hitd = 1.f;
    bool hit = false;
#pragma unroll
    for (int m = 0; m < NNODE; m++) {
        float d = x - (x0 + hw * CHEB[m]);
        if (fabsf(d) < 1e-10f) { hit = true; hitn = snum[base + m]; hitd = sden[base + m]; d = 1.f; }
        float wm = __fdividef(LAMB[m], d);
        wn = fmaf(wm, snum[base + m], wn);
        wd = fmaf(wm, sden[base + m], wd);
    }
    return hit ? __fdividef(hitn, hitd) : __fdividef(wn, wd);
}

__device__ __forceinline__ float interp_g(float x, float xmin, float w, float hw,
                                          float invw,
                                          const float2* __restrict__ nodes) {
    int c = (int)((x - xmin) * invw);
    c = (c < 0) ? 0 : ((c >= NI) ? NI - 1 : c);
    const float x0 = xmin + (c + 0.5f) * w;
    const float2* nb = nodes + c * NNODE;
    float wn = 0.f, wd = 0.f, hitn = 0.f, hitd = 1.f;
    bool hit = false;
#pragma unroll
    for (int m = 0; m < NNODE; m++) {
        float2 nd = nb[m];
        float d = x - (x0 + hw * CHEB[m]);
        if (fabsf(d) < 1e-10f) { hit = true; hitn = nd.x; hitd = nd.y; d = 1.f; }
        float wm = __fdividef(LAMB[m], d);
        wn = fmaf(wm, nd.x, wn);
        wd = fmaf(wm, nd.y, wd);
    }
    return hit ? __fdividef(hitn, hitd) : __fdividef(wn, wd);
}

// ---------------------------------------------------------------------------
// Kernel 1: two S=768 attentions via node eval + interpolation, + sentence
// copy. grid (32, 3), block 512. Reads only harness inputs (no wait).
// ---------------------------------------------------------------------------
__global__ void __launch_bounds__(512) attn_pre_interp(const float* __restrict__ sent,
                                                       const float* __restrict__ ts,
                                                       const float* __restrict__ oth,
                                                       const float* __restrict__ sd,
                                                       const float* __restrict__ ss) {
    const int b = blockIdx.x, task = blockIdx.y;
    const int tid = threadIdx.x, lane = tid & 31, wid = tid >> 5;

    if (task == 2) {
        for (int i = tid; i < 768; i += 512) g_fused[b * 2304 + i] = sent[b * 768 + i];
        GDC_RELEASE;
        return;
    }

    const float* q = (task == 0) ? oth : ss;
    const float* k = (task == 0) ? ts  : ss;
    const float* v = (task == 0) ? ts  : sd;
    const int outoff = (task == 0) ? 1536 : 768;

    __shared__ __align__(16) float sq[768], sk[768], sv[768];
    __shared__ float snum[NODES], sden[NODES];
    __shared__ float red[32];

    for (int i = tid; i < 768; i += 512) {
        sq[i] = q[b * 768 + i];
        sk[i] = k[b * 768 + i];
        sv[i] = v[b * 768 + i];
    }
    __syncthreads();

    float lmin = 1e30f, lmax = -1e30f;
    for (int i = tid; i < 768; i += 512) {
        float x = sq[i];
        lmin = fminf(lmin, x); lmax = fmaxf(lmax, x);
    }
#pragma unroll
    for (int o = 16; o > 0; o >>= 1) {
        lmin = fminf(lmin, __shfl_xor_sync(0xffffffffu, lmin, o));
        lmax = fmaxf(lmax, __shfl_xor_sync(0xffffffffu, lmax, o));
    }
    if (lane == 0) { red[wid] = lmin; red[16 + wid] = lmax; }
    __syncthreads();
    float xmin = red[0], xmax = red[16];
#pragma unroll
    for (int i = 1; i < 16; i++) { xmin = fminf(xmin, red[i]); xmax = fmaxf(xmax, red[16 + i]); }

    const float w  = (xmax - xmin) * (1.f / NI);
    const float hw = 0.5f * w;

    for (int m = wid; m < NODES; m += 16) {
        const int c = m / NNODE, mm = m - c * NNODE;
        const float Xl = (xmin + (c + 0.5f) * w + hw * CHEB[mm]) * LOG2E;
        float sn = 0.f, sd_ = 0.f;
        for (int t = lane; t < 768; t += 32) {
            float e = ex2f(Xl * sk[t]);
            sd_ += e;
            sn = fmaf(e, sv[t], sn);
        }
        sn = wredsum(sn); sd_ = wredsum(sd_);
        if (lane == 0) { snum[m] = sn; sden[m] = sd_; }
    }
    __syncthreads();

    const float invw = __fdividef(1.f, w);
    for (int s = tid; s < 768; s += 512)
        g_fused[b * 2304 + outoff + s] = interp_s(sq[s], xmin, w, hw, invw, snum, sden);
    GDC_RELEASE;
}

// ---------------------------------------------------------------------------
// Kernel 2 (fat): fused-attention node table + shared projections.
// PDL: proj-task-0 blocks read only harness inputs -> no wait (full overlap
// with kernel 1). Node blocks + proj tasks 1/2 wait before touching g_fused.
// ---------------------------------------------------------------------------
__global__ void __launch_bounds__(256) fat_kernel(const float* __restrict__ sent,
                                                  const float* __restrict__ Wsh) {
    const int bx = blockIdx.x;
    const int tid = threadIdx.x, lane = tid & 31, wid = tid >> 5;

    if (bx < FAT_NODE_BLOCKS) {
        const int b = bx & 31, grp = bx >> 5;

        __shared__ __align__(16) float sf[2304];
        __shared__ float red[16];

        GDC_WAIT;
        for (int i = tid; i < 576; i += 256)
            *reinterpret_cast<float4*>(sf + i * 4) =
                *reinterpret_cast<const float4*>(g_fused + b * 2304 + i * 4);
        __syncthreads();

        float lmin = 1e30f, lmax = -1e30f;
        for (int i = tid; i < 2304; i += 256) {
            float x = sf[i];
            lmin = fminf(lmin, x); lmax = fmaxf(lmax, x);
        }
#pragma unroll
        for (int o = 16; o > 0; o >>= 1) {
            lmin = fminf(lmin, __shfl_xor_sync(0xffffffffu, lmin, o));
            lmax = fmaxf(lmax, __shfl_xor_sync(0xffffffffu, lmax, o));
        }
        if (lane == 0) { red[wid] = lmin; red[8 + wid] = lmax; }
        __syncthreads();
        float xmin = red[0], xmax = red[8];
#pragma unroll
        for (int i = 1; i < 8; i++) { xmin = fminf(xmin, red[i]); xmax = fmaxf(xmax, red[8 + i]); }

        if (grp == 0 && tid == 0) { g_frange[b * 2] = xmin; g_frange[b * 2 + 1] = xmax; }

        const float w  = (xmax - xmin) * (1.f / NI);
        const float hw = 0.5f * w;
        const int m0 = grp * (NODES / NGRP);

        for (int m = m0 + wid; m < m0 + NODES / NGRP; m += 8) {
            const int c = m / NNODE, mm = m - c * NNODE;
            const float Xl = (xmin + (c + 0.5f) * w + hw * CHEB[mm]) * LOG2E;
            float sn = 0.f, sd_ = 0.f;
            for (int t = lane; t < 2304; t += 32) {
                float f = sf[t];
                float e = ex2f(Xl * f);
                sd_ += e;
                sn = fmaf(e, f, sn);     // v == f
            }
            sn = wredsum(sn); sd_ = wredsum(sd_);
            if (lane == 0) g_nodes[b * NODES + m] = make_float2(sn, sd_);
        }
        GDC_RELEASE;
        return;
    }

    // ----- proj section -----
    const int p    = bx - FAT_NODE_BLOCKS;
    const int task = p / (PROJ_KC * 2);
    const int rem  = p - task * PROJ_KC * 2;
    const int kc   = rem >> 1;
    const int jt   = rem & 1;
    const int j    = jt * 256 + tid;       // 0..511
    const int i0   = kc * PROJ_KCH;

    __shared__ __align__(16) float xs[PROJ_KCH][36];

    if (task != 0) GDC_WAIT;               // task 0 reads only 'sent' — no wait
    for (int e = tid; e < PROJ_KCH * 32; e += 256) {
        int i = e & 31, b = e >> 5;
        xs[i][b] = (task == 0) ? sent[b * 768 + i0 + i]
                               : g_fused[b * 2304 + 768 * task + i0 + i];
    }
    __syncthreads();

    float acc[32];
#pragma unroll
    for (int b = 0; b < 32; b++) acc[b] = 0.f;

#pragma unroll
    for (int i = 0; i < PROJ_KCH; i++) {
        float wv = Wsh[(i0 + i) * 512 + j];
#pragma unroll
        for (int b4 = 0; b4 < 8; b4++) {
            float4 x = *reinterpret_cast<const float4*>(&xs[i][b4 * 4]);
            acc[b4 * 4 + 0] = fmaf(x.x, wv, acc[b4 * 4 + 0]);
            acc[b4 * 4 + 1] = fmaf(x.y, wv, acc[b4 * 4 + 1]);
            acc[b4 * 4 + 2] = fmaf(x.z, wv, acc[b4 * 4 + 2]);
            acc[b4 * 4 + 3] = fmaf(x.w, wv, acc[b4 * 4 + 3]);
        }
    }

#pragma unroll
    for (int b = 0; b < 32; b++)
        g_pp[(((size_t)task * PROJ_KC + kc) * 32 + b) * 512 + j] = acc[b];
    GDC_RELEASE;
}

// ---------------------------------------------------------------------------
// Kernel 3: mlp1 with fused assemble. grid MLP_KC (120), block 256.
// PDL prologue: preload this thread's full W1 column slice (independent of
// kernel 2) into registers BEFORE the wait.
// ---------------------------------------------------------------------------
__global__ void __launch_bounds__(256) mlp1_fused(const float* __restrict__ W1,
                                                  const float* __restrict__ bsh) {
    const int kc = blockIdx.x;
    const int i0 = kc * MLP_KCH;
    const int j  = threadIdx.x;

    __shared__ __align__(16) float xs[MLP_KCH][36];

    float wreg[MLP_KCH];
#pragma unroll
    for (int i = 0; i < MLP_KCH; i++) wreg[i] = W1[(i0 + i) * 256 + j];   // pre-wait

    GDC_WAIT;

    if (kc < 72) {
        for (int e = threadIdx.x; e < MLP_KCH * 32; e += 256) {
            int ii = e & 31, b = e >> 5;
            const float xmin = g_frange[b * 2], xmax = g_frange[b * 2 + 1];
            const float w  = (xmax - xmin) * (1.f / NI);
            const float hw = 0.5f * w;
            const float invw = __fdividef(1.f, w);
            const float x = g_fused[b * 2304 + i0 + ii];
            xs[ii][b] = interp_g(x, xmin, w, hw, invw, g_nodes + b * NODES);
        }
    } else {
        const int t0   = i0 - 2304;
        const int task = t0 >> 9;
        const int jj0  = t0 & 511;
        for (int e = threadIdx.x; e < MLP_KCH * 32; e += 256) {
            int jl = e & 31, b = e >> 5;
            const int jj = jj0 + jl;
            float a = bsh[jj];
            const float* pp = g_pp + (((size_t)task * PROJ_KC) * 32 + b) * 512 + jj;
#pragma unroll
            for (int s = 0; s < PROJ_KC; s++) a += pp[(size_t)s * 32 * 512];
            xs[jl][b] = a;
        }
    }
    __syncthreads();

    float acc[32];
#pragma unroll
    for (int b = 0; b < 32; b++) acc[b] = 0.f;

#pragma unroll
    for (int i = 0; i < MLP_KCH; i++) {
        float w = wreg[i];
#pragma unroll
        for (int b4 = 0; b4 < 8; b4++) {
            float4 x = *reinterpret_cast<const float4*>(&xs[i][b4 * 4]);
            acc[b4 * 4 + 0] = fmaf(x.x, w, acc[b4 * 4 + 0]);
            acc[b4 * 4 + 1] = fmaf(x.y, w, acc[b4 * 4 + 1]);
            acc[b4 * 4 + 2] = fmaf(x.z, w, acc[b4 * 4 + 2]);
            acc[b4 * 4 + 3] = fmaf(x.w, w, acc[b4 * 4 + 3]);
        }
    }

#pragma unroll
    for (int b = 0; b < 32; b++)
        g_h_part[((size_t)kc * 32 + b) * 256 + j] = acc[b];
    GDC_RELEASE;
}

// ---------------------------------------------------------------------------
// Kernel 4: reduce mlp1 partials + bias + relu, then mlp2 + sigmoid.
// grid 32, block 1024. PDL prologue: preload b1/W2/b2 pre-wait.
// ---------------------------------------------------------------------------
__global__ void __launch_bounds__(1024) mlp_tail(const float* __restrict__ b1,
                                                 const float* __restrict__ W2,
                                                 const float* __restrict__ b2,
                                                 float* __restrict__ out) {
    const int b = blockIdx.x;
    const int j = threadIdx.x & 255;
    const int qt = threadIdx.x >> 8;          // 0..3
    const int w = threadIdx.x >> 5, lane = threadIdx.x & 31;

    __shared__ float sred[4][256];
    __shared__ float h[256];

    // pre-wait: weights/biases (independent of kernel 3)
    const float bias1 = (qt == 0) ? b1[j] : 0.f;
    float w2reg[8];
    float bias2 = 0.f;
    if (w < 7) {
#pragma unroll
        for (int q = 0; q < 8; q++) w2reg[q] = W2[(q * 32 + lane) * 7 + w];
        bias2 = b2[w];
    }

    GDC_WAIT;

    const float* src = g_h_part + ((size_t)(qt * 30) * 32 + b) * 256 + j;
    float a0 = 0.f, a1 = 0.f, a2 = 0.f, a3 = 0.f, a4 = 0.f, a5 = 0.f;
#pragma unroll
    for (int i = 0; i < 30; i += 6) {
        a0 += src[(size_t)(i + 0) * 32 * 256];
        a1 += src[(size_t)(i + 1) * 32 * 256];
        a2 += src[(size_t)(i + 2) * 32 * 256];
        a3 += src[(size_t)(i + 3) * 32 * 256];
        a4 += src[(size_t)(i + 4) * 32 * 256];
        a5 += src[(size_t)(i + 5) * 32 * 256];
    }
    sred[qt][j] = ((a0 + a1) + (a2 + a3)) + (a4 + a5);
    __syncthreads();

    if (qt == 0) {
        float v = ((sred[0][j] + sred[1][j]) + (sred[2][j] + sred[3][j])) + bias1;
        h[j] = fmaxf(v, 0.f);
    }
    __syncthreads();

    if (w < 7) {
        float s = 0.f;
#pragma unroll
        for (int q = 0; q < 8; q++) s = fmaf(h[q * 32 + lane], w2reg[q], s);
#pragma unroll
        for (int o = 16; o > 0; o >>= 1) s += __shfl_xor_sync(0xffffffffu, s, o);
        if (lane == 0) out[b * 7 + w] = 1.f / (1.f + __expf(-(s + bias2)));
    }
}

// -------- host: PDL launches ------------------------------------------------
template <typename... Args>
static void launch_pdl(void (*kern)(Args...), dim3 grid, dim3 block, Args... args) {
    cudaLaunchConfig_t cfg = {};
    cfg.gridDim = grid;
    cfg.blockDim = block;
    cudaLaunchAttribute attr[1];
    attr[0].id = cudaLaunchAttributeProgrammaticStreamSerialization;
    attr[0].val.programmaticStreamSerializationAllowed = 1;
    cfg.attrs = attr;
    cfg.numAttrs = 1;
    cudaLaunchKernelEx(&cfg, kern, args...);
}

extern "C" void kernel_launch(void* const* d_in, const int* in_sizes, int n_in,
                              void* d_out, int out_size) {
    const float* sent = (const float*)d_in[0];
    const float* ts   = (const float*)d_in[1];
    const float* oth  = (const float*)d_in[2];
    const float* sd   = (const float*)d_in[3];
    const float* ss   = (const float*)d_in[4];
    const float* Wsh  = (const float*)d_in[5];
    const float* bsh  = (const float*)d_in[6];
    const float* W1   = (const float*)d_in[7];
    const float* b1   = (const float*)d_in[8];
    const float* W2   = (const float*)d_in[9];
    const float* b2   = (const float*)d_in[10];
    float* out = (float*)d_out;

    attn_pre_interp<<<dim3(32, 3), 512>>>(sent, ts, oth, sd, ss);
    launch_pdl(fat_kernel, dim3(FAT_NODE_BLOCKS + FAT_PROJ_BLOCKS), dim3(256), sent, Wsh);
    launch_pdl(mlp1_fused, dim3(MLP_KC), dim3(256), W1, bsh);
    launch_pdl(mlp_tail, dim3(32), dim3(1024), b1, W2, b2, out);
}